// round 1
// baseline (speedup 1.0000x reference)
#include <cuda_runtime.h>
#include <cmath>
#include <stdint.h>

#define AMAX 1024
#define WORDS (AMAX / 32)
#define BMAX 2
#define CMAX 80

// Scratch (no dynamic allocation allowed)
__device__ float4 g_boxes[BMAX * AMAX];                          // 32 KB
__device__ unsigned g_adj[BMAX * AMAX * WORDS];                  // 256 KB (IoU>0.5 bit matrix per batch)
__device__ unsigned long long g_keys[BMAX * CMAX * AMAX];        // 1.3 MB (sorted keys per (b,c))
__device__ unsigned g_keep[BMAX * CMAX * WORDS];                 // 20 KB (keep bitmask per (b,c))

__device__ __forceinline__ float4 regress_box(const float* __restrict__ reg,
                                              const float* __restrict__ anchors,
                                              int b, int t, int A, float Wf, float Hf) {
    float ax1 = anchors[4 * t + 0], ay1 = anchors[4 * t + 1];
    float ax2 = anchors[4 * t + 2], ay2 = anchors[4 * t + 3];
    float w = ax2 - ax1, h = ay2 - ay1;
    float cx = ax1 + 0.5f * w, cy = ay1 + 0.5f * h;
    const float* rb = reg + (size_t)b * 4 * A;
    float dx = rb[0 * A + t] * 0.1f;
    float dy = rb[1 * A + t] * 0.1f;
    float dw = rb[2 * A + t] * 0.2f;
    float dh = rb[3 * A + t] * 0.2f;
    float pcx = cx + dx * w, pcy = cy + dy * h;
    float pw = expf(dw) * w, ph = expf(dh) * h;
    float4 r;
    r.x = fmaxf(pcx - 0.5f * pw, 0.0f);
    r.y = fmaxf(pcy - 0.5f * ph, 0.0f);
    r.z = fminf(pcx + 0.5f * pw, Wf);
    r.w = fminf(pcy + 0.5f * ph, Hf);
    return r;
}

// Heterogeneous prep kernel:
//   blocks [0, B*128):        box regression + IoU adjacency matrix (8 rows per block)
//   blocks [B*128, +B*C):     per-(b,c) key build + bitonic sort -> g_keys
__global__ void __launch_bounds__(256) prep_kernel(
    const float* __restrict__ cls, const float* __restrict__ reg,
    const float* __restrict__ anchors, int A, int B, int C, float Wf, float Hf) {
    __shared__ __align__(16) unsigned char smem_raw[AMAX * 16];  // 16 KB, aliased
    int bid = blockIdx.x;
    int tid = threadIdx.x;
    int nAdjBlocks = B * (AMAX / 8);

    if (bid < nAdjBlocks) {
        // ---- adjacency path ----
        float4* sb = (float4*)smem_raw;
        int b = bid / (AMAX / 8);
        int chunk = bid % (AMAX / 8);
        #pragma unroll
        for (int t = tid; t < AMAX; t += 256) {
            float4 bx = regress_box(reg, anchors, b, t, A, Wf, Hf);
            sb[t] = bx;
            if (chunk == 0) g_boxes[b * AMAX + t] = bx;  // one block per batch persists boxes
        }
        __syncthreads();

        int lane = tid & 31, wid = tid >> 5;
        int row = chunk * 8 + wid;
        float4 bi = sb[row];
        float ai = (bi.z - bi.x) * (bi.w - bi.y);
        unsigned mybits = 0;
        #pragma unroll
        for (int w = 0; w < WORDS; ++w) {
            float4 bj = sb[w * 32 + lane];
            float ix1 = fmaxf(bi.x, bj.x), iy1 = fmaxf(bi.y, bj.y);
            float ix2 = fminf(bi.z, bj.z), iy2 = fminf(bi.w, bj.w);
            float inter = fmaxf(ix2 - ix1, 0.0f) * fmaxf(iy2 - iy1, 0.0f);
            float aj = (bj.z - bj.x) * (bj.w - bj.y);
            float den = fmaxf((ai + aj) - inter, 1e-9f);
            bool adj = __fdiv_rn(inter, den) > 0.5f;   // IEEE div: match XLA at the 0.5 boundary
            unsigned bal = __ballot_sync(0xffffffffu, adj);
            if (lane == w) mybits = bal;
        }
        g_adj[((size_t)b * AMAX + row) * WORDS + lane] = mybits;
    } else {
        // ---- sort path: one (b,c) per block ----
        unsigned long long* keys = (unsigned long long*)smem_raw;  // 8 KB used
        int bc = bid - nAdjBlocks;
        const float* sp = cls + (size_t)bc * A;
        #pragma unroll
        for (int i = tid; i < AMAX; i += 256) {
            float s = sp[i];
            // ascending sort => descending score, ties broken by ascending index (stable argsort)
            keys[i] = ((unsigned long long)(~__float_as_uint(s)) << 32) | (unsigned)i;
        }
        __syncthreads();
        for (unsigned k = 2; k <= AMAX; k <<= 1) {
            for (unsigned j = k >> 1; j > 0; j >>= 1) {
                #pragma unroll
                for (int i = tid; i < AMAX; i += 256) {
                    unsigned ixj = (unsigned)i ^ j;
                    if (ixj > (unsigned)i) {
                        unsigned long long a = keys[i], b2 = keys[ixj];
                        bool up = (((unsigned)i & k) == 0);
                        if ((a > b2) == up) { keys[i] = b2; keys[ixj] = a; }
                    }
                }
                __syncthreads();
            }
        }
        #pragma unroll
        for (int i = tid; i < AMAX; i += 256)
            g_keys[(size_t)bc * AMAX + i] = keys[i];
    }
}

// Greedy NMS reduce: one 32-thread warp per (b,c). 1024-bit removed-mask
// distributed one word per lane; adjacency rows prefetched 16 deep.
__global__ void __launch_bounds__(32) greedy_kernel(int C) {
    __shared__ unsigned long long keys[AMAX];
    int bc = blockIdx.x;
    int b = bc / C;
    int lane = threadIdx.x;
    const unsigned long long* gk = g_keys + (size_t)bc * AMAX;
    for (int i = lane; i < AMAX; i += 32) keys[i] = gk[i];
    __syncwarp();

    const unsigned* adjb = g_adj + (size_t)b * AMAX * WORDS;
    unsigned remv = 0, kw = 0;
    const int D = 16;
    unsigned pref[D];
    #pragma unroll
    for (int d = 0; d < D; ++d) {
        unsigned idx = (unsigned)keys[d] & (AMAX - 1);
        pref[d] = __ldg(&adjb[idx * WORDS + lane]);
    }
    #pragma unroll 16
    for (int r = 0; r < AMAX; ++r) {
        unsigned long long kk = keys[r];
        unsigned idx = (unsigned)kk & (AMAX - 1);
        float sc = __uint_as_float(~(unsigned)(kk >> 32));
        unsigned adjw = pref[r & (D - 1)];
        if (r + D < AMAX) {  // rolling prefetch
            unsigned nidx = (unsigned)keys[r + D] & (AMAX - 1);
            pref[r & (D - 1)] = __ldg(&adjb[nidx * WORDS + lane]);
        }
        unsigned ow = idx >> 5;
        unsigned oword = __shfl_sync(0xffffffffu, remv, ow);
        bool kept = (sc > 0.05f) && !((oword >> (idx & 31)) & 1u);
        if (kept) {
            remv |= adjw;                       // suppress neighbors (self-bit harmless: never revisited)
            if (lane == (int)ow) kw |= 1u << (idx & 31);
        }
    }
    g_keep[bc * WORDS + lane] = kw;
}

// Assemble (B,C,A,5): [keep?score:0, keep?box:0]
__global__ void __launch_bounds__(256) output_kernel(const float* __restrict__ cls,
                                                     float* __restrict__ out, int C) {
    int g = blockIdx.x * 256 + threadIdx.x;  // flat (b,c,a)
    int a = g & (AMAX - 1);
    int bc = g >> 10;
    int b = bc / C;
    bool kp = (g_keep[bc * WORDS + (a >> 5)] >> (a & 31)) & 1u;
    float s = cls[g];
    float4 bx = g_boxes[b * AMAX + a];
    float* o = out + (size_t)g * 5;
    o[0] = kp ? s : 0.0f;
    o[1] = kp ? bx.x : 0.0f;
    o[2] = kp ? bx.y : 0.0f;
    o[3] = kp ? bx.z : 0.0f;
    o[4] = kp ? bx.w : 0.0f;
}

extern "C" void kernel_launch(void* const* d_in, const int* in_sizes, int n_in,
                              void* d_out, int out_size) {
    // metadata order: image, cls_pred, reg_pred, anchors
    const float* cls = (const float*)d_in[1];
    const float* reg = (const float*)d_in[2];
    const float* anchors = (const float*)d_in[3];

    int A = in_sizes[3] / 4;                 // 1024
    int B = in_sizes[2] / (4 * A);           // 2
    int C = in_sizes[1] / (B * A);           // 80
    long long hw = (long long)in_sizes[0] / (3LL * B);
    int H = (int)(sqrt((double)hw) + 0.5);   // 2048 (image assumed square; only shape is used)
    float Hf = (float)H, Wf = (float)H;

    int nAdj = B * (AMAX / 8);               // 256 adjacency blocks
    int nSort = B * C;                       // 160 sort blocks
    prep_kernel<<<nAdj + nSort, 256>>>(cls, reg, anchors, A, B, C, Wf, Hf);
    greedy_kernel<<<B * C, 32>>>(C);
    int total = B * C * AMAX;
    output_kernel<<<total / 256, 256>>>(cls, (float*)d_out, C);
}

// round 2
// speedup vs baseline: 1.5374x; 1.5374x over previous
#include <cuda_runtime.h>
#include <cmath>
#include <stdint.h>

#define AMAX 1024
#define WORDS 32
#define BMAX 2
#define CMAX 80
#define KCAP 16

// Scratch (static device arrays; no dynamic allocation allowed)
__device__ float4 g_boxes[BMAX * AMAX];                 // 32 KB
__device__ unsigned g_adjT[BMAX * WORDS * AMAX];        // 256 KB, transposed: [b][word][box]

__device__ __forceinline__ float4 regress_box(const float* __restrict__ reg,
                                              const float* __restrict__ anchors,
                                              int b, int t, int A, float Wf, float Hf) {
    float ax1 = anchors[4 * t + 0], ay1 = anchors[4 * t + 1];
    float ax2 = anchors[4 * t + 2], ay2 = anchors[4 * t + 3];
    float w = ax2 - ax1, h = ay2 - ay1;
    float cx = ax1 + 0.5f * w, cy = ay1 + 0.5f * h;
    const float* rb = reg + (size_t)b * 4 * A;
    float dx = rb[0 * A + t] * 0.1f;
    float dy = rb[1 * A + t] * 0.1f;
    float dw = rb[2 * A + t] * 0.2f;
    float dh = rb[3 * A + t] * 0.2f;
    float pcx = cx + dx * w, pcy = cy + dy * h;
    float pw = expf(dw) * w, ph = expf(dh) * h;
    float4 r;
    r.x = fmaxf(pcx - 0.5f * pw, 0.0f);
    r.y = fmaxf(pcy - 0.5f * ph, 0.0f);
    r.z = fminf(pcx + 0.5f * pw, Wf);
    r.w = fminf(pcy + 0.5f * ph, Hf);
    return r;
}

// Kernel A: box regression + IoU>0.5 adjacency bit-matrix (per batch, shared by all classes).
// Grid: B*64 blocks, 512 threads; each block handles 16 rows of the 1024x1024 matrix.
__global__ void __launch_bounds__(512) adj_kernel(
    const float* __restrict__ reg, const float* __restrict__ anchors,
    int A, float Wf, float Hf) {
    __shared__ float4 sb[AMAX];  // 16 KB
    int b = blockIdx.x >> 6;
    int chunk = blockIdx.x & 63;
    int tid = threadIdx.x;

    for (int t = tid; t < AMAX; t += 512) {
        float4 bx = regress_box(reg, anchors, b, t, A, Wf, Hf);
        sb[t] = bx;
        if (chunk == 0) g_boxes[b * AMAX + t] = bx;  // persist boxes once per batch
    }
    __syncthreads();

    int lane = tid & 31, wid = tid >> 5;
    int row = chunk * 16 + wid;
    float4 bi = sb[row];
    float ai = (bi.z - bi.x) * (bi.w - bi.y);
    unsigned mybits = 0;
    #pragma unroll
    for (int w = 0; w < WORDS; ++w) {
        float4 bj = sb[w * 32 + lane];
        float ix1 = fmaxf(bi.x, bj.x), iy1 = fmaxf(bi.y, bj.y);
        float ix2 = fminf(bi.z, bj.z), iy2 = fminf(bi.w, bj.w);
        float inter = fmaxf(ix2 - ix1, 0.0f) * fmaxf(iy2 - iy1, 0.0f);
        float aj = (bj.z - bj.x) * (bj.w - bj.y);
        float den = fmaxf((ai + aj) - inter, 1e-9f);
        bool adj = __fdiv_rn(inter, den) > 0.5f;  // IEEE div: match XLA at the 0.5 boundary
        unsigned bal = __ballot_sync(0xffffffffu, adj);
        if (lane == w) mybits = bal;
    }
    // Transposed store: word `lane` of row `row` -> g_adjT[b][lane][row]
    g_adjT[((size_t)b * WORDS + lane) * AMAX + row] = mybits;
}

// Kernel B: per-(b,c) NMS as a fixpoint on the suppression DAG + fused output write.
// One 1024-thread block per (b,c); thread i owns box i.
// State bits rebuilt each iteration via warp ballots (warp w owns state word w).
__global__ void __launch_bounds__(1024) nms_kernel(
    const float* __restrict__ cls, float* __restrict__ out, int C) {
    __shared__ float ssc[AMAX];
    __shared__ unsigned kept_s[WORDS], dec_s[WORDS];
    int bc = blockIdx.x;
    int b = bc / C;
    int i = threadIdx.x, lane = i & 31, wid = i >> 5;

    float s = cls[(size_t)bc * AMAX + i];
    ssc[i] = s;
    __syncthreads();

    // Build list of higher-ranked adjacent neighbors (rank: score desc, index asc).
    const unsigned* adjT = g_adjT + (size_t)b * WORDS * AMAX;
    unsigned short list[KCAP];
    int cnt = 0;
    #pragma unroll
    for (int w = 0; w < WORDS; ++w) {
        unsigned m = adjT[w * AMAX + i];            // coalesced across the warp
        if (w == (i >> 5)) m &= ~(1u << (i & 31));  // drop self bit
        while (m) {
            int bit = __ffs(m) - 1; m &= m - 1;
            int j = w * 32 + bit;
            float sj = ssc[j];
            if (sj > s || (sj == s && j < i)) {
                if (cnt < KCAP) list[cnt] = (unsigned short)j;
                cnt++;
            }
        }
    }
    bool ovf = cnt > KCAP;  // rare high-degree fallback: rescan row each iteration

    bool valid = s > 0.05f;
    bool mykept = valid && (cnt == 0);
    bool mydec = !valid || (cnt == 0);

    // Fixpoint: each iteration the min-rank undecided box decides -> terminates.
    for (int iter = 0; iter <= AMAX; ++iter) {
        unsigned kb = __ballot_sync(0xffffffffu, mykept);
        unsigned db = __ballot_sync(0xffffffffu, mydec);
        if (lane == 0) { kept_s[wid] = kb; dec_s[wid] = db; }
        int nundec = __syncthreads_count(!mydec);  // barrier: publishes state words
        if (nundec == 0) break;
        if (!mydec) {
            bool sup = false, alld = true;
            if (!ovf) {
                for (int k = 0; k < cnt; ++k) {
                    int j = list[k];
                    unsigned bit = 1u << (j & 31);
                    if (kept_s[j >> 5] & bit) sup = true;
                    if (!(dec_s[j >> 5] & bit)) alld = false;
                }
            } else {
                #pragma unroll
                for (int w = 0; w < WORDS; ++w) {
                    unsigned m = adjT[w * AMAX + i];
                    if (w == (i >> 5)) m &= ~(1u << (i & 31));
                    while (m) {
                        int bit = __ffs(m) - 1; m &= m - 1;
                        int j = w * 32 + bit;
                        float sj = ssc[j];
                        if (sj > s || (sj == s && j < i)) {
                            unsigned bb = 1u << (j & 31);
                            if (kept_s[j >> 5] & bb) sup = true;
                            if (!(dec_s[j >> 5] & bb)) alld = false;
                        }
                    }
                }
            }
            if (sup)       { mydec = true; mykept = false; }
            else if (alld) { mydec = true; mykept = true;  }
        }
        __syncthreads();  // reads done before next iteration's state writes
    }

    // Fused output: (b,c,a,5) = [keep?score:0, keep?box:0]
    float4 bx = g_boxes[b * AMAX + i];
    float* o = out + ((size_t)bc * AMAX + i) * 5;
    o[0] = mykept ? s    : 0.0f;
    o[1] = mykept ? bx.x : 0.0f;
    o[2] = mykept ? bx.y : 0.0f;
    o[3] = mykept ? bx.z : 0.0f;
    o[4] = mykept ? bx.w : 0.0f;
}

extern "C" void kernel_launch(void* const* d_in, const int* in_sizes, int n_in,
                              void* d_out, int out_size) {
    // metadata order: image, cls_pred, reg_pred, anchors
    const float* cls = (const float*)d_in[1];
    const float* reg = (const float*)d_in[2];
    const float* anchors = (const float*)d_in[3];

    int A = in_sizes[3] / 4;                 // 1024
    int B = in_sizes[2] / (4 * A);           // 2
    int C = in_sizes[1] / (B * A);           // 80
    long long hw = (long long)in_sizes[0] / (3LL * B);
    int H = (int)(sqrt((double)hw) + 0.5);   // 2048 (image used for shape only)
    float Hf = (float)H, Wf = (float)H;

    adj_kernel<<<B * 64, 512>>>(reg, anchors, A, Wf, Hf);
    nms_kernel<<<B * C, 1024>>>(cls, (float*)d_out, C);
}

// round 3
// speedup vs baseline: 2.5146x; 1.6356x over previous
#include <cuda_runtime.h>
#include <cmath>
#include <stdint.h>

#define AMAX 1024
#define WORDS 32
#define BMAX 2
#define CMAX 80
#define NK 8           // compact neighbor-list capacity (per box)

// Scratch (static device arrays; no dynamic allocation allowed)
__device__ float4 g_boxes[BMAX * AMAX];                   // 32 KB
__device__ unsigned g_adjT[BMAX * WORDS * AMAX];          // 256 KB (fallback for degree>NK)
__device__ unsigned short g_nbr[BMAX * AMAX * NK];        // 32 KB compact neighbor lists
__device__ int g_ncnt[BMAX * AMAX];                       // 8 KB degrees

__device__ __forceinline__ float4 regress_box(const float* __restrict__ reg,
                                              const float* __restrict__ anchors,
                                              int b, int t, int A, float Wf, float Hf) {
    float ax1 = anchors[4 * t + 0], ay1 = anchors[4 * t + 1];
    float ax2 = anchors[4 * t + 2], ay2 = anchors[4 * t + 3];
    float w = ax2 - ax1, h = ay2 - ay1;
    float cx = ax1 + 0.5f * w, cy = ay1 + 0.5f * h;
    const float* rb = reg + (size_t)b * 4 * A;
    float dx = rb[0 * A + t] * 0.1f;
    float dy = rb[1 * A + t] * 0.1f;
    float dw = rb[2 * A + t] * 0.2f;
    float dh = rb[3 * A + t] * 0.2f;
    float pcx = cx + dx * w, pcy = cy + dy * h;
    float pw = expf(dw) * w, ph = expf(dh) * h;
    float4 r;
    r.x = fmaxf(pcx - 0.5f * pw, 0.0f);
    r.y = fmaxf(pcy - 0.5f * ph, 0.0f);
    r.z = fminf(pcx + 0.5f * pw, Wf);
    r.w = fminf(pcy + 0.5f * ph, Hf);
    return r;
}

// Kernel A: box regression + IoU>0.5 adjacency. Emits per-box compact neighbor
// lists (class-agnostic; shared by all 80 classes) plus bit-matrix fallback.
// Grid: B*32 blocks x 1024 threads; warp w of block handles row chunk*32+w.
__global__ void __launch_bounds__(1024) adj_kernel(
    const float* __restrict__ reg, const float* __restrict__ anchors,
    int A, float Wf, float Hf) {
    __shared__ float4 sb[AMAX];  // 16 KB
    int b = blockIdx.x >> 5;
    int chunk = blockIdx.x & 31;
    int tid = threadIdx.x;

    {
        float4 bx = regress_box(reg, anchors, b, tid, A, Wf, Hf);
        sb[tid] = bx;
        if (chunk == 0) g_boxes[b * AMAX + tid] = bx;  // persist once per batch
    }
    __syncthreads();

    int lane = tid & 31, wid = tid >> 5;
    int row = chunk * 32 + wid;
    float4 bi = sb[row];
    float ai = (bi.z - bi.x) * (bi.w - bi.y);
    unsigned mybits = 0;
    #pragma unroll
    for (int w = 0; w < WORDS; ++w) {
        float4 bj = sb[w * 32 + lane];
        float ix1 = fmaxf(bi.x, bj.x), iy1 = fmaxf(bi.y, bj.y);
        float ix2 = fminf(bi.z, bj.z), iy2 = fminf(bi.w, bj.w);
        float inter = fmaxf(ix2 - ix1, 0.0f) * fmaxf(iy2 - iy1, 0.0f);
        float aj = (bj.z - bj.x) * (bj.w - bj.y);
        float den = fmaxf((ai + aj) - inter, 1e-9f);
        bool adj = __fdiv_rn(inter, den) > 0.5f;  // IEEE div: match XLA at 0.5 boundary
        unsigned bal = __ballot_sync(0xffffffffu, adj);
        if (lane == w) mybits = bal;
    }
    // lane l now holds this row's adjacency bits for columns [l*32, l*32+32)
    unsigned m = mybits;
    if (lane == (row >> 5)) m &= ~(1u << (row & 31));  // drop self
    g_adjT[((size_t)b * WORDS + lane) * AMAX + row] = m;  // transposed, self-free

    // Compact neighbor list: shuffle prefix-sum of per-lane popcounts.
    int cnt = __popc(m);
    int scan = cnt;
    #pragma unroll
    for (int d = 1; d < 32; d <<= 1) {
        int t = __shfl_up_sync(0xffffffffu, scan, d);
        if (lane >= d) scan += t;
    }
    int excl = scan - cnt;
    int total = __shfl_sync(0xffffffffu, scan, 31);
    unsigned short* np = g_nbr + ((size_t)b * AMAX + row) * NK;
    unsigned mm = m;
    int pos = excl;
    while (mm && pos < NK) {
        int t2 = __ffs(mm) - 1; mm &= mm - 1;
        np[pos++] = (unsigned short)(lane * 32 + t2);
    }
    if (lane == 0) g_ncnt[b * AMAX + row] = total;
}

// Kernel B: per-(b,c) NMS fixpoint on the suppression DAG + fused coalesced output.
// One 1024-thread block per (b,c); thread i owns box i. Warp w owns state word w.
__global__ void __launch_bounds__(1024, 2) nms_kernel(
    const float* __restrict__ cls, float* __restrict__ out, int C) {
    __shared__ float ssc[AMAX];
    __shared__ float4 sbox[AMAX];
    __shared__ unsigned kept_s[WORDS], dec_s[WORDS];
    int bc = blockIdx.x;
    int b = bc / C;
    int i = threadIdx.x, lane = i & 31, wid = i >> 5;

    float s = cls[(size_t)bc * AMAX + i];
    ssc[i] = s;
    sbox[i] = g_boxes[b * AMAX + i];
    __syncthreads();

    // Fetch compact neighbor list (one uint4) and degree.
    int total = g_ncnt[b * AMAX + i];
    uint4 nv = *(const uint4*)&g_nbr[((size_t)b * AMAX + i) * NK];
    bool ovf = total > NK;
    int cnt = ovf ? 0 : total;

    // Mask of neighbors that outrank me (score desc, index asc).
    unsigned hmask = 0;
    {
        unsigned nw0 = nv.x, nw1 = nv.y, nw2 = nv.z, nw3 = nv.w;
        unsigned words[4] = {nw0, nw1, nw2, nw3};
        #pragma unroll
        for (int k = 0; k < NK; ++k) {
            if (k < cnt) {
                int j = (words[k >> 1] >> ((k & 1) * 16)) & 0xFFFF;
                float sj = ssc[j];
                if (sj > s || (sj == s && j < i)) hmask |= 1u << k;
            }
        }
    }

    const unsigned* adjT = g_adjT + (size_t)b * WORDS * AMAX;
    bool valid = s > 0.05f;
    bool mydec, mykept;
    if (ovf) { mydec = !valid; mykept = false; }
    else     { mydec = !valid || (hmask == 0); mykept = valid && (hmask == 0); }

    // Fixpoint: min-rank undecided box always decides each round -> terminates.
    for (int iter = 0; iter <= AMAX; ++iter) {
        unsigned kb = __ballot_sync(0xffffffffu, mykept);
        unsigned db = __ballot_sync(0xffffffffu, mydec);
        if (lane == 0) { kept_s[wid] = kb; dec_s[wid] = db; }
        int nundec = __syncthreads_count(!mydec);  // barrier publishes state
        if (nundec == 0) break;
        if (!mydec) {
            bool sup = false, alld = true;
            if (!ovf) {
                unsigned words[4] = {nv.x, nv.y, nv.z, nv.w};
                #pragma unroll
                for (int k = 0; k < NK; ++k) {
                    if ((hmask >> k) & 1u) {
                        int j = (words[k >> 1] >> ((k & 1) * 16)) & 0xFFFF;
                        unsigned bb = 1u << (j & 31);
                        if (kept_s[j >> 5] & bb) sup = true;
                        if (!(dec_s[j >> 5] & bb)) alld = false;
                    }
                }
            } else {  // rare high-degree fallback: rescan full adjacency row
                #pragma unroll
                for (int w = 0; w < WORDS; ++w) {
                    unsigned mm = adjT[w * AMAX + i];
                    while (mm) {
                        int bit = __ffs(mm) - 1; mm &= mm - 1;
                        int j = w * 32 + bit;
                        float sj = ssc[j];
                        if (sj > s || (sj == s && j < i)) {
                            unsigned bb = 1u << (j & 31);
                            if (kept_s[j >> 5] & bb) sup = true;
                            if (!(dec_s[j >> 5] & bb)) alld = false;
                        }
                    }
                }
            }
            if (sup)       { mydec = true; mykept = false; }
            else if (alld) { mydec = true; mykept = true;  }
        }
        __syncthreads();  // reads complete before next publish
    }
    // Final publish (loop normally breaks right after a publish; this also
    // covers the no-break path) so the output pass can read any box's bit.
    {
        unsigned kb = __ballot_sync(0xffffffffu, mykept);
        if (lane == 0) kept_s[wid] = kb;
        __syncthreads();
    }

    // Fused output, fully coalesced over the flat (A*5)-float block region.
    const float* sboxf = (const float*)sbox;
    float* obase = out + (size_t)bc * AMAX * 5;
    #pragma unroll
    for (int r = 0; r < 5; ++r) {
        int idx = r * AMAX + i;
        int a = idx / 5;
        int f = idx - a * 5;
        bool kp = (kept_s[a >> 5] >> (a & 31)) & 1u;
        float v = 0.0f;
        if (kp) v = (f == 0) ? ssc[a] : sboxf[a * 4 + (f - 1)];
        obase[idx] = v;
    }
}

extern "C" void kernel_launch(void* const* d_in, const int* in_sizes, int n_in,
                              void* d_out, int out_size) {
    // metadata order: image, cls_pred, reg_pred, anchors
    const float* cls = (const float*)d_in[1];
    const float* reg = (const float*)d_in[2];
    const float* anchors = (const float*)d_in[3];

    int A = in_sizes[3] / 4;                 // 1024
    int B = in_sizes[2] / (4 * A);           // 2
    int C = in_sizes[1] / (B * A);           // 80
    long long hw = (long long)in_sizes[0] / (3LL * B);
    int H = (int)(sqrt((double)hw) + 0.5);   // 2048 (image used for shape only)
    float Hf = (float)H, Wf = (float)H;

    adj_kernel<<<B * 32, 1024>>>(reg, anchors, A, Wf, Hf);
    nms_kernel<<<B * C, 1024>>>(cls, (float*)d_out, C);
}

// round 4
// speedup vs baseline: 2.7270x; 1.0845x over previous
#include <cuda_runtime.h>
#include <cmath>
#include <stdint.h>

#define AMAX 1024
#define WORDS 32
#define BMAX 2
#define CMAX 80
#define NK 8           // compact neighbor-list capacity (per box)

// Scratch (static device arrays; no dynamic allocation allowed)
__device__ float4 g_boxes[BMAX * AMAX];                   // 32 KB
__device__ unsigned g_adjT[BMAX * WORDS * AMAX];          // 256 KB (fallback for degree>NK)
__device__ unsigned short g_nbr[BMAX * AMAX * NK];        // 32 KB compact neighbor lists
__device__ int g_ncnt[BMAX * AMAX];                       // 8 KB degrees

__device__ __forceinline__ float4 regress_box(const float* __restrict__ reg,
                                              const float* __restrict__ anchors,
                                              int b, int t, int A, float Wf, float Hf) {
    float ax1 = anchors[4 * t + 0], ay1 = anchors[4 * t + 1];
    float ax2 = anchors[4 * t + 2], ay2 = anchors[4 * t + 3];
    float w = ax2 - ax1, h = ay2 - ay1;
    float cx = ax1 + 0.5f * w, cy = ay1 + 0.5f * h;
    const float* rb = reg + (size_t)b * 4 * A;
    float dx = rb[0 * A + t] * 0.1f;
    float dy = rb[1 * A + t] * 0.1f;
    float dw = rb[2 * A + t] * 0.2f;
    float dh = rb[3 * A + t] * 0.2f;
    float pcx = cx + dx * w, pcy = cy + dy * h;
    float pw = expf(dw) * w, ph = expf(dh) * h;
    float4 r;
    r.x = fmaxf(pcx - 0.5f * pw, 0.0f);
    r.y = fmaxf(pcy - 0.5f * ph, 0.0f);
    r.z = fminf(pcx + 0.5f * pw, Wf);
    r.w = fminf(pcy + 0.5f * ph, Hf);
    return r;
}

// Kernel A: box regression + IoU>0.5 adjacency; emits compact per-box neighbor
// lists (class-agnostic, shared by all 80 classes) + bit-matrix fallback.
// Grid: B*32 blocks x 1024 threads; warp w handles row chunk*32+w.
__global__ void __launch_bounds__(1024) adj_kernel(
    const float* __restrict__ reg, const float* __restrict__ anchors,
    int A, float Wf, float Hf) {
    __shared__ float4 sb[AMAX];  // 16 KB
    int b = blockIdx.x >> 5;
    int chunk = blockIdx.x & 31;
    int tid = threadIdx.x;

    {
        float4 bx = regress_box(reg, anchors, b, tid, A, Wf, Hf);
        sb[tid] = bx;
        if (chunk == 0) g_boxes[b * AMAX + tid] = bx;  // persist once per batch
    }
    __syncthreads();

    int lane = tid & 31, wid = tid >> 5;
    int row = chunk * 32 + wid;
    float4 bi = sb[row];
    float ai = (bi.z - bi.x) * (bi.w - bi.y);
    unsigned mybits = 0;
    #pragma unroll
    for (int w = 0; w < WORDS; ++w) {
        float4 bj = sb[w * 32 + lane];
        float ix1 = fmaxf(bi.x, bj.x), iy1 = fmaxf(bi.y, bj.y);
        float ix2 = fminf(bi.z, bj.z), iy2 = fminf(bi.w, bj.w);
        float inter = fmaxf(ix2 - ix1, 0.0f) * fmaxf(iy2 - iy1, 0.0f);
        float aj = (bj.z - bj.x) * (bj.w - bj.y);
        float den = fmaxf((ai + aj) - inter, 1e-9f);
        bool adj = __fdiv_rn(inter, den) > 0.5f;  // IEEE div: match XLA at 0.5 boundary
        unsigned bal = __ballot_sync(0xffffffffu, adj);
        if (lane == w) mybits = bal;
    }
    unsigned m = mybits;
    if (lane == (row >> 5)) m &= ~(1u << (row & 31));    // drop self bit
    g_adjT[((size_t)b * WORDS + lane) * AMAX + row] = m; // transposed, self-free

    // Compact neighbor list via shuffle prefix-sum of per-lane popcounts.
    int cnt = __popc(m);
    int scan = cnt;
    #pragma unroll
    for (int d = 1; d < 32; d <<= 1) {
        int t = __shfl_up_sync(0xffffffffu, scan, d);
        if (lane >= d) scan += t;
    }
    int excl = scan - cnt;
    int total = __shfl_sync(0xffffffffu, scan, 31);
    unsigned short* np = g_nbr + ((size_t)b * AMAX + row) * NK;
    unsigned mm = m;
    int pos = excl;
    while (mm && pos < NK) {
        int t2 = __ffs(mm) - 1; mm &= mm - 1;
        np[pos++] = (unsigned short)(lane * 32 + t2);
    }
    if (lane == 0) g_ncnt[b * AMAX + row] = total;
}

// Kernel B: per-(b,c) NMS via ASYNC monotone dataflow (no barriers in the loop)
// + fused coalesced output. One 1024-thread block per (b,c); thread i owns box i
// and its private state bytes sdec[i]/skept[i] (0->1 monotone).
__global__ void __launch_bounds__(1024, 2) nms_kernel(
    const float* __restrict__ cls, float* __restrict__ out, int C) {
    __shared__ float ssc[AMAX];
    __shared__ float4 sbox[AMAX];
    __shared__ volatile unsigned char skept[AMAX];
    __shared__ volatile unsigned char sdec[AMAX];
    int bc = blockIdx.x;
    int b = bc / C;
    int i = threadIdx.x;

    // Stage inputs (latency overlapped before the barrier).
    float s = cls[(size_t)bc * AMAX + i];
    int total = g_ncnt[b * AMAX + i];
    uint4 nv = *(const uint4*)&g_nbr[((size_t)b * AMAX + i) * NK];
    ssc[i] = s;
    sbox[i] = g_boxes[b * AMAX + i];
    sdec[i] = 0;
    skept[i] = 0;
    __syncthreads();

    bool ovf = total > NK;   // rare high-degree fallback: rescan global row
    int cnt = ovf ? 0 : total;

    // Extract higher-ranked neighbors (rank: score desc, index asc) to registers.
    unsigned short js[NK];
    int nh = 0;
    {
        unsigned words[4] = {nv.x, nv.y, nv.z, nv.w};
        #pragma unroll
        for (int k = 0; k < NK; ++k) {
            if (k < cnt) {
                int j = (words[k >> 1] >> ((k & 1) * 16)) & 0xFFFF;
                float sj = ssc[j];
                if (sj > s || (sj == s && j < i)) js[nh++] = (unsigned short)j;
            }
        }
    }

    bool valid = s > 0.05f;
    bool mykept;
    if (!valid) {
        mykept = false;
        sdec[i] = 1;                                   // never kept, never suppresses
    } else if (!ovf && nh == 0) {
        mykept = true;
        skept[i] = 1; __threadfence_block(); sdec[i] = 1;
    } else {
        // Spin until all higher neighbors decided or one of them is kept.
        // Progress: the min-rank undecided box always has all higher neighbors
        // decided, so it decides on its next poll -> no deadlock.
        const unsigned* adjT = g_adjT + (size_t)b * WORDS * AMAX;
        for (;;) {
            bool sup = false, alld = true;
            if (!ovf) {
                unsigned dmask = 0;
                for (int k = 0; k < nh; ++k)
                    if (sdec[js[k]]) dmask |= 1u << k; else alld = false;
                __threadfence_block();                 // acquire: dec before kept
                while (dmask) {
                    int k = __ffs(dmask) - 1; dmask &= dmask - 1;
                    if (skept[js[k]]) { sup = true; break; }
                }
            } else {
                #pragma unroll
                for (int w = 0; w < WORDS; ++w) {
                    unsigned mm = adjT[w * AMAX + i];
                    while (mm) {
                        int bit = __ffs(mm) - 1; mm &= mm - 1;
                        int j = w * 32 + bit;
                        float sj = ssc[j];
                        if (sj > s || (sj == s && j < i)) {
                            if (sdec[j]) {
                                __threadfence_block();
                                if (skept[j]) sup = true;
                            } else alld = false;
                        }
                    }
                }
            }
            if (sup)  { mykept = false; sdec[i] = 1; break; }
            if (alld) { mykept = true;
                        skept[i] = 1; __threadfence_block(); sdec[i] = 1; break; }
        }
    }
    __syncthreads();  // all decided; skept[] stable for the output pass

    // Fused output, fully coalesced over the flat (A*5)-float block region.
    const float* sboxf = (const float*)sbox;
    float* obase = out + (size_t)bc * AMAX * 5;
    #pragma unroll
    for (int r = 0; r < 5; ++r) {
        int idx = r * AMAX + i;
        int a = idx / 5;
        int f = idx - a * 5;
        float v = 0.0f;
        if (skept[a]) v = (f == 0) ? ssc[a] : sboxf[a * 4 + (f - 1)];
        obase[idx] = v;
    }
    (void)mykept;
}

extern "C" void kernel_launch(void* const* d_in, const int* in_sizes, int n_in,
                              void* d_out, int out_size) {
    // metadata order: image, cls_pred, reg_pred, anchors
    const float* cls = (const float*)d_in[1];
    const float* reg = (const float*)d_in[2];
    const float* anchors = (const float*)d_in[3];

    int A = in_sizes[3] / 4;                 // 1024
    int B = in_sizes[2] / (4 * A);           // 2
    int C = in_sizes[1] / (B * A);           // 80
    long long hw = (long long)in_sizes[0] / (3LL * B);
    int H = (int)(sqrt((double)hw) + 0.5);   // 2048 (image used for shape only)
    float Hf = (float)H, Wf = (float)H;

    adj_kernel<<<B * 32, 1024>>>(reg, anchors, A, Wf, Hf);
    nms_kernel<<<B * C, 1024>>>(cls, (float*)d_out, C);
}